// round 2
// baseline (speedup 1.0000x reference)
#include <cuda_runtime.h>
#include <cstdint>
#include <cstddef>

#define H    512
#define H4   2048
#define E    112
#define OPS  12
#define GRID 128
#define TPB  256
#define EPC  4      // h-elements owned per CTA (128*4 = 512)

// ---------------- persistent device state (scratch; re-initialized every launch) -------------
__device__ float    g_gumbel[E * OPS];
__device__ float    g_preX0[OPS * H4];      // emb[a] @ Wih0^T
__device__ float    g_b0[H4];               // bih0 + bhh0
__device__ float    g_b1[H4];               // bih1 + bhh1
__device__ float    g_h0buf[2][H];          // double-buffered h0 broadcast
__device__ float    g_h1buf[2][H];          // double-buffered h1 broadcast
__device__ float    g_part[GRID * OPS];     // per-CTA partial logits
__device__ unsigned g_ctrA, g_ctrB, g_ctrC; // phase arrival counters (monotonic)
__device__ unsigned g_actFlag;              // ((step+1)<<8) | action

// ---------------- helpers ----------------
__device__ __forceinline__ unsigned ld_acq(const unsigned* p) {
    unsigned v;
    asm volatile("ld.acquire.gpu.b32 %0, [%1];" : "=r"(v) : "l"(p) : "memory");
    return v;
}
__device__ __forceinline__ float sigm(float x) { return 1.f / (1.f + expf(-x)); }
__device__ __forceinline__ float wsum(float v) {
#pragma unroll
    for (int o = 16; o; o >>= 1) v += __shfl_xor_sync(0xffffffffu, v, o);
    return v;
}
__device__ __forceinline__ float bits_to_gumbel(unsigned b) {
    // exact JAX uniform: f = bitcast((bits>>9)|0x3f800000) - 1 ; u = max(tiny, f*(1-tiny)+tiny)
    float f = __uint_as_float((b >> 9) | 0x3f800000u) - 1.0f;
    float u = fmaxf(1.17549435e-38f, f * 1.0f + 1.17549435e-38f);
    return -logf(-logf(u));
}

// ---------------- init kernels ----------------
__global__ void k_init(const float* __restrict__ h0) {
    int t = threadIdx.x;
    if (t == 0) { g_ctrA = 0u; g_ctrB = 0u; g_ctrC = 0u; g_actFlag = 0u; }
    if (t < H) {
        g_h0buf[1][t] = h0[t];        // step0 reads "prev" = buffer 1
        g_h1buf[1][t] = h0[H + t];
    }
}

__global__ void k_bias(const float* __restrict__ bih0, const float* __restrict__ bhh0,
                       const float* __restrict__ bih1, const float* __restrict__ bhh1) {
    int r = blockIdx.x * blockDim.x + threadIdx.x;
    if (r < H4) {
        g_b0[r] = bih0[r] + bhh0[r];
        g_b1[r] = bih1[r] + bhh1[r];
    }
}

// JAX >= 0.5 default: threefry_partitionable=True.
// bits32[i] = fold_in: (b1, b2) = threefry2x32(key=(0,42), (hi32(i)=0, lo32(i)=i)); out = b1 ^ b2
__global__ void k_gumbel() {
    int i = blockIdx.x * blockDim.x + threadIdx.x;
    if (i >= E * OPS) return;  // 1344
    const unsigned k0 = 0u, k1 = 42u;
    const unsigned k2 = k0 ^ k1 ^ 0x1BD11BDAu;
    unsigned x0 = 0u + k0;            // high 32 bits of uint64 counter = 0
    unsigned x1 = (unsigned)i + k1;   // low 32 bits of uint64 counter = i
#define TF_ROT(r) { x0 += x1; x1 = (x1 << (r)) | (x1 >> (32 - (r))); x1 ^= x0; }
    TF_ROT(13) TF_ROT(15) TF_ROT(26) TF_ROT(6)  x0 += k1; x1 += k2 + 1u;
    TF_ROT(17) TF_ROT(29) TF_ROT(16) TF_ROT(24) x0 += k2; x1 += k0 + 2u;
    TF_ROT(13) TF_ROT(15) TF_ROT(26) TF_ROT(6)  x0 += k0; x1 += k1 + 3u;
    TF_ROT(17) TF_ROT(29) TF_ROT(16) TF_ROT(24) x0 += k1; x1 += k2 + 4u;
    TF_ROT(13) TF_ROT(15) TF_ROT(26) TF_ROT(6)  x0 += k2; x1 += k0 + 5u;
#undef TF_ROT
    g_gumbel[i] = bits_to_gumbel(x0 ^ x1);
}

// preX0[a][r] = dot(Wih0[r,:], emb[a,:])  — one warp per (a,r)
__global__ void k_prex(const float* __restrict__ Wih0, const float* __restrict__ emb) {
    int w    = (blockIdx.x * blockDim.x + threadIdx.x) >> 5;
    int lane = threadIdx.x & 31;
    if (w >= OPS * H4) return;
    int a = w / H4, r = w % H4;
    const float4* wp = (const float4*)(Wih0 + (size_t)r * H);
    const float4* xp = (const float4*)(emb + (size_t)a * H);
    float acc = 0.f;
#pragma unroll
    for (int i = lane; i < H / 4; i += 32) {
        float4 u = wp[i], v = xp[i];
        acc = fmaf(u.x, v.x, acc); acc = fmaf(u.y, v.y, acc);
        acc = fmaf(u.z, v.z, acc); acc = fmaf(u.w, v.w, acc);
    }
    acc = wsum(acc);
    if (lane == 0) g_preX0[a * H4 + r] = acc;
}

// ---------------- the persistent controller kernel ----------------
// SMEM float layout
#define SM_W0   0
#define SM_WI1  (16 * H)
#define SM_WH1  (32 * H)
#define SM_X    (48 * H)
#define SM_Y    (SM_X + H)
#define SM_GATE (SM_Y + H)
#define SM_RED  (SM_GATE + 16)
#define SM_HM   (SM_RED + 32)
#define SM_C0   (SM_HM + 4)
#define SM_C1   (SM_C0 + 4)
#define SM_A    (SM_C1 + 4)
#define SMEM_FLOATS (SM_A + 4)
#define SMEM_BYTES  (SMEM_FLOATS * 4)

__global__ void __launch_bounds__(TPB, 1) k_ctrl(
    const float* __restrict__ Whh0, const float* __restrict__ Wih1, const float* __restrict__ Whh1,
    const float* __restrict__ c0in,
    const float* __restrict__ cW1, const float* __restrict__ cb1,
    const float* __restrict__ cW2, const float* __restrict__ cb2,
    const unsigned* __restrict__ tempPtr, float* __restrict__ out)
{
    extern __shared__ float sm[];
    float* sW0   = sm + SM_W0;
    float* sWi1  = sm + SM_WI1;
    float* sWh1  = sm + SM_WH1;
    float* sX    = sm + SM_X;
    float* sY    = sm + SM_Y;
    float* sGate = sm + SM_GATE;
    float* sRed  = sm + SM_RED;
    float* sHm   = sm + SM_HM;
    float* sC0   = sm + SM_C0;
    float* sC1   = sm + SM_C1;
    int*   sA    = (int*)(sm + SM_A);

    const int tid  = threadIdx.x, cta = blockIdx.x;
    const int lane = tid & 31, warp = tid >> 5;
    const int base0 = cta * EPC;

    // one-time: stage this CTA's 16 gate rows of each LSTM matrix into SMEM
    for (int idx = tid; idx < 16 * H; idx += TPB) {
        int lr = idx >> 9, col = idx & (H - 1);
        int grow = (lr & 3) * H + base0 + (lr >> 2);   // lr = le*4 + gate
        size_t go = (size_t)grow * H + col;
        sW0[idx]  = Whh0[go];
        sWi1[idx] = Wih1[go];
        sWh1[idx] = Whh1[go];
    }
    if (tid < EPC) {
        sC0[tid] = c0in[base0 + tid];
        sC1[tid] = c0in[H + base0 + tid];
    }
    unsigned tb = tempPtr[0];  // temperature may be int32 or float32
    const float tempf = (tb & 0x7f800000u) ? __uint_as_float(tb) : (float)(int)tb;
    __syncthreads();

    for (int s = 0; s < E; s++) {
        const int cur = s & 1, prev = cur ^ 1;

        // ================= phase A: LSTM cell 0 =================
        if (tid == 0) {
            int a = -1;
            if (s > 0) {
                unsigned v;
                do { v = ld_acq(&g_actFlag); } while ((int)(v >> 8) < s);
                a = (int)(v & 0xffu);
            }
            sA[0] = a;
        }
        __syncthreads();
        const int act = sA[0];
        for (int j = tid; j < H; j += TPB) sX[j] = __ldcg(&g_h0buf[prev][j]);
        __syncthreads();
#pragma unroll
        for (int lr = warp; lr < 16; lr += 8) {
            const float4* wp = (const float4*)(sW0 + lr * H);
            const float4* xp = (const float4*)sX;
            float acc = 0.f;
#pragma unroll
            for (int i = lane; i < H / 4; i += 32) {
                float4 u = wp[i], v = xp[i];
                acc = fmaf(u.x, v.x, acc); acc = fmaf(u.y, v.y, acc);
                acc = fmaf(u.z, v.z, acc); acc = fmaf(u.w, v.w, acc);
            }
            acc = wsum(acc);
            if (lane == 0) sGate[lr] = acc;
        }
        __syncthreads();
        if (tid < 16) {
            int grow = (tid & 3) * H + base0 + (tid >> 2);
            float v = sGate[tid] + g_b0[grow];
            if (act >= 0) v += g_preX0[act * H4 + grow];
            sGate[tid] = v;
        }
        __syncthreads();
        if (tid < EPC) {
            float gi = sGate[tid * 4 + 0], gf = sGate[tid * 4 + 1];
            float gg = sGate[tid * 4 + 2], go = sGate[tid * 4 + 3];
            float c  = sC0[tid];
            float c2 = sigm(gf) * c + sigm(gi) * tanhf(gg);
            float h2 = sigm(go) * tanhf(c2);
            sC0[tid] = c2;
            g_h0buf[cur][base0 + tid] = h2;
        }
        __syncthreads();
        if (tid == 0) {
            __threadfence();
            atomicAdd(&g_ctrA, 1u);
            unsigned tgt = (unsigned)(s + 1) * GRID;
            while (ld_acq(&g_ctrA) < tgt) {}
        }
        __syncthreads();

        // ================= phase B: LSTM cell 1 =================
        for (int j = tid; j < H; j += TPB) {
            sX[j] = __ldcg(&g_h0buf[cur][j]);
            sY[j] = __ldcg(&g_h1buf[prev][j]);
        }
        __syncthreads();
#pragma unroll
        for (int lr = warp; lr < 16; lr += 8) {
            const float4* wp = (const float4*)(sWi1 + lr * H);
            const float4* hp = (const float4*)(sWh1 + lr * H);
            const float4* xp = (const float4*)sX;
            const float4* yp = (const float4*)sY;
            float acc = 0.f;
#pragma unroll
            for (int i = lane; i < H / 4; i += 32) {
                float4 u = wp[i], v = xp[i];
                acc = fmaf(u.x, v.x, acc); acc = fmaf(u.y, v.y, acc);
                acc = fmaf(u.z, v.z, acc); acc = fmaf(u.w, v.w, acc);
                float4 a = hp[i], b = yp[i];
                acc = fmaf(a.x, b.x, acc); acc = fmaf(a.y, b.y, acc);
                acc = fmaf(a.z, b.z, acc); acc = fmaf(a.w, b.w, acc);
            }
            acc = wsum(acc);
            if (lane == 0) sGate[lr] = acc;
        }
        __syncthreads();
        if (tid < 16) {
            int grow = (tid & 3) * H + base0 + (tid >> 2);
            sGate[tid] += g_b1[grow];
        }
        __syncthreads();
        if (tid < EPC) {
            float gi = sGate[tid * 4 + 0], gf = sGate[tid * 4 + 1];
            float gg = sGate[tid * 4 + 2], go = sGate[tid * 4 + 3];
            float c  = sC1[tid];
            float c2 = sigm(gf) * c + sigm(gi) * tanhf(gg);
            float h2 = sigm(go) * tanhf(c2);
            sC1[tid] = c2;
            g_h1buf[cur][base0 + tid] = h2;
        }
        __syncthreads();
        if (tid == 0) {
            __threadfence();
            atomicAdd(&g_ctrB, 1u);
            unsigned tgt = (unsigned)(s + 1) * GRID;
            while (ld_acq(&g_ctrB) < tgt) {}
        }
        __syncthreads();

        // ================= phase C: MLP hidden + partial logits =================
        for (int j = tid; j < H; j += TPB) sX[j] = __ldcg(&g_h1buf[cur][j]);
        __syncthreads();
        {
            // hmlp[base0..base0+3]: column access of cW1[s][j][r], float4 over 4 owned rows
            const float* basep = cW1 + (size_t)s * H * H + base0;
            float4 acc = make_float4(0.f, 0.f, 0.f, 0.f);
            for (int j = tid; j < H; j += TPB) {
                float4 w = __ldcg((const float4*)(basep + (size_t)j * H));
                float  x = sX[j];
                acc.x = fmaf(x, w.x, acc.x); acc.y = fmaf(x, w.y, acc.y);
                acc.z = fmaf(x, w.z, acc.z); acc.w = fmaf(x, w.w, acc.w);
            }
            acc.x = wsum(acc.x); acc.y = wsum(acc.y);
            acc.z = wsum(acc.z); acc.w = wsum(acc.w);
            if (lane == 0) {
                sRed[warp * 4 + 0] = acc.x; sRed[warp * 4 + 1] = acc.y;
                sRed[warp * 4 + 2] = acc.z; sRed[warp * 4 + 3] = acc.w;
            }
        }
        __syncthreads();
        if (tid < EPC) {
            float v = 0.f;
#pragma unroll
            for (int w = 0; w < 8; w++) v += sRed[w * 4 + tid];
            v += cb1[(size_t)s * H + base0 + tid];
            sHm[tid] = fmaxf(v, 0.f);
        }
        __syncthreads();
        if (tid < OPS) {
            float p = 0.f;
#pragma unroll
            for (int k = 0; k < EPC; k++)
                p += sHm[k] * cW2[((size_t)s * H + base0 + k) * OPS + tid];
            g_part[cta * OPS + tid] = p;
        }
        __syncthreads();
        if (tid == 0) { __threadfence(); atomicAdd(&g_ctrC, 1u); }

        // ================= phase D: logits reduce + sample (CTA0 only) =================
        if (cta == 0) {
            if (tid == 0) {
                unsigned tgt = (unsigned)(s + 1) * GRID;
                while (ld_acq(&g_ctrC) < tgt) {}
            }
            __syncthreads();
            if (warp == 0) {
                const float NEGINF = __int_as_float(0xff800000);
                float logit = NEGINF;
                if (lane < OPS) {
                    float a0 = 0.f, a1 = 0.f, a2 = 0.f, a3 = 0.f;
#pragma unroll 8
                    for (int c2 = 0; c2 < GRID; c2 += 4) {
                        a0 += __ldcg(&g_part[(c2 + 0) * OPS + lane]);
                        a1 += __ldcg(&g_part[(c2 + 1) * OPS + lane]);
                        a2 += __ldcg(&g_part[(c2 + 2) * OPS + lane]);
                        a3 += __ldcg(&g_part[(c2 + 3) * OPS + lane]);
                    }
                    logit = (cb2[s * OPS + lane] + ((a0 + a1) + (a2 + a3))) / tempf;
                }
                float m = logit;
#pragma unroll
                for (int o = 16; o; o >>= 1) m = fmaxf(m, __shfl_xor_sync(0xffffffffu, m, o));
                float ex   = (lane < OPS) ? expf(logit - m) : 0.f;
                float ssum = wsum(ex);
                float lse  = m + logf(ssum);
                float lp   = logit - lse;
                float et   = (lane < OPS) ? (-expf(lp) * lp) : 0.f;
                float ent  = wsum(et);
                float key  = (lane < OPS) ? (logit + g_gumbel[s * OPS + lane]) : NEGINF;
                float bk = key; int bi = lane;
#pragma unroll
                for (int o = 16; o; o >>= 1) {
                    float ok = __shfl_xor_sync(0xffffffffu, bk, o);
                    int   oi = __shfl_xor_sync(0xffffffffu, bi, o);
                    if (ok > bk || (ok == bk && oi < bi)) { bk = ok; bi = oi; }
                }
                float lpa = __shfl_sync(0xffffffffu, lp, bi);
                if (lane == 0) {
                    out[s]         = (float)bi;
                    out[E + s]     = lpa;
                    out[2 * E + s] = ent;
                    atomicExch(&g_actFlag, (((unsigned)(s + 1)) << 8) | (unsigned)bi);
                }
            }
            __syncthreads();
        }
    }
}

// ---------------- launch ----------------
extern "C" void kernel_launch(void* const* d_in, const int* in_sizes, int n_in,
                              void* d_out, int out_size) {
    const unsigned* temp = (const unsigned*)d_in[0];
    const float* h0   = (const float*)d_in[1];
    const float* c0   = (const float*)d_in[2];
    const float* Wih0 = (const float*)d_in[3];
    const float* Whh0 = (const float*)d_in[4];
    const float* bih0 = (const float*)d_in[5];
    const float* bhh0 = (const float*)d_in[6];
    const float* Wih1 = (const float*)d_in[7];
    const float* Whh1 = (const float*)d_in[8];
    const float* bih1 = (const float*)d_in[9];
    const float* bhh1 = (const float*)d_in[10];
    const float* emb  = (const float*)d_in[11];
    const float* cW1  = (const float*)d_in[12];
    const float* cb1  = (const float*)d_in[13];
    const float* cW2  = (const float*)d_in[14];
    const float* cb2  = (const float*)d_in[15];
    float* out = (float*)d_out;

    cudaFuncSetAttribute(k_ctrl, cudaFuncAttributeMaxDynamicSharedMemorySize, SMEM_BYTES);

    k_init<<<1, 512>>>(h0);
    k_bias<<<8, 256>>>(bih0, bhh0, bih1, bhh1);
    k_gumbel<<<3, 512>>>();
    k_prex<<<(OPS * H4) / 8, 256>>>(Wih0, emb);
    k_ctrl<<<GRID, TPB, SMEM_BYTES>>>(Whh0, Wih1, Whh1, c0, cW1, cb1, cW2, cb2, temp, out);
}

// round 3
// speedup vs baseline: 1.7422x; 1.7422x over previous
#include <cuda_runtime.h>
#include <cstdint>
#include <cstddef>

#define H    512
#define H4   2048
#define E    112
#define OPS  12
#define GRID 128
#define TPB  256
#define EPC  4      // h-elements owned per CTA (128*4 = 512)

// ---------------- persistent device state (re-initialized every launch by k_setup) ----------
__device__ float    g_gumbel[E * OPS];
__device__ float    g_preX0[OPS * H4];            // emb[a] @ Wih0^T
__device__ float    g_b0[H4];                     // bih0 + bhh0
__device__ float    g_b1[H4];                     // bih1 + bhh1
__device__ float    g_h0buf[2][H];                // double-buffered h0 broadcast
__device__ float    g_h1buf[2][H];                // double-buffered h1 broadcast
__device__ __align__(16) float g_part[OPS * GRID];// partial logits [op][cta]
__device__ unsigned g_flagA[GRID * 8];            // padded flag arrays (32B/CTA)
__device__ unsigned g_flagB[GRID * 8];
__device__ unsigned g_flagC[GRID * 8];

// ---------------- helpers ----------------
__device__ __forceinline__ unsigned ld_rlx(const unsigned* p) {
    unsigned v;
    asm volatile("ld.relaxed.gpu.b32 %0, [%1];" : "=r"(v) : "l"(p) : "memory");
    return v;
}
__device__ __forceinline__ void st_rel(unsigned* p, unsigned v) {
    asm volatile("st.release.gpu.b32 [%0], %1;" :: "l"(p), "r"(v) : "memory");
}
__device__ __forceinline__ void fence_acq() {
    asm volatile("fence.acq_rel.gpu;" ::: "memory");
}
__device__ __forceinline__ void cp16(uint32_t dst, const void* src) {
    asm volatile("cp.async.cg.shared.global [%0], [%1], 16;" :: "r"(dst), "l"(src));
}
__device__ __forceinline__ void cp_commit() { asm volatile("cp.async.commit_group;" ::: "memory"); }
__device__ __forceinline__ void cp_wait0()  { asm volatile("cp.async.wait_group 0;" ::: "memory"); }

__device__ __forceinline__ float sigm(float x) { return 1.f / (1.f + expf(-x)); }
__device__ __forceinline__ float wsum(float v) {
#pragma unroll
    for (int o = 16; o; o >>= 1) v += __shfl_xor_sync(0xffffffffu, v, o);
    return v;
}
// warp0-collective: wait until all GRID flags >= tgt
__device__ __forceinline__ void waitflags(const unsigned* f, unsigned tgt) {
    const int lane = threadIdx.x & 31;
    bool ok = false;
    do {
        unsigned m0 = ld_rlx(f + (lane      ) * 8);
        unsigned m1 = ld_rlx(f + (lane + 32) * 8);
        unsigned m2 = ld_rlx(f + (lane + 64) * 8);
        unsigned m3 = ld_rlx(f + (lane + 96) * 8);
        ok = (m0 >= tgt) & (m1 >= tgt) & (m2 >= tgt) & (m3 >= tgt);
    } while (!__all_sync(0xffffffffu, ok));
    fence_acq();
}
__device__ __forceinline__ float bits_to_gumbel(unsigned b) {
    float f = __uint_as_float((b >> 9) | 0x3f800000u) - 1.0f;
    float u = fmaxf(1.17549435e-38f, f * 1.0f + 1.17549435e-38f);
    return -logf(-logf(u));
}
// dot(w[0:512], x[0:512]) across the calling warp (all 32 lanes)
__device__ __forceinline__ float dot512(const float* __restrict__ w, const float* __restrict__ x) {
    const int lane = threadIdx.x & 31;
    const float4* wp = (const float4*)w;
    const float4* xp = (const float4*)x;
    float acc = 0.f;
#pragma unroll
    for (int i = lane; i < H / 4; i += 32) {
        float4 u = wp[i], v = xp[i];
        acc = fmaf(u.x, v.x, acc); acc = fmaf(u.y, v.y, acc);
        acc = fmaf(u.z, v.z, acc); acc = fmaf(u.w, v.w, acc);
    }
    return wsum(acc);
}

// ---------------- fused setup kernel ----------------
__global__ void k_setup(const float* __restrict__ h0,
                        const float* __restrict__ bih0, const float* __restrict__ bhh0,
                        const float* __restrict__ bih1, const float* __restrict__ bhh1) {
    int i = blockIdx.x * blockDim.x + threadIdx.x;   // 0..2047
    if (i < GRID * 8) { g_flagA[i] = 0u; g_flagB[i] = 0u; g_flagC[i] = 0u; }
    if (i < H) {
        g_h0buf[1][i] = h0[i];           // step0 reads "prev" = buffer 1
        g_h1buf[1][i] = h0[H + i];
    }
    if (i < H4) {
        g_b0[i] = bih0[i] + bhh0[i];
        g_b1[i] = bih1[i] + bhh1[i];
    }
    if (i < E * OPS) {
        // JAX partitionable threefry: (b1,b2)=threefry2x32((0,42),(0,i)); bits = b1^b2
        const unsigned k0 = 0u, k1 = 42u;
        const unsigned k2 = k0 ^ k1 ^ 0x1BD11BDAu;
        unsigned x0 = 0u + k0;
        unsigned x1 = (unsigned)i + k1;
#define TF_ROT(r) { x0 += x1; x1 = (x1 << (r)) | (x1 >> (32 - (r))); x1 ^= x0; }
        TF_ROT(13) TF_ROT(15) TF_ROT(26) TF_ROT(6)  x0 += k1; x1 += k2 + 1u;
        TF_ROT(17) TF_ROT(29) TF_ROT(16) TF_ROT(24) x0 += k2; x1 += k0 + 2u;
        TF_ROT(13) TF_ROT(15) TF_ROT(26) TF_ROT(6)  x0 += k0; x1 += k1 + 3u;
        TF_ROT(17) TF_ROT(29) TF_ROT(16) TF_ROT(24) x0 += k1; x1 += k2 + 4u;
        TF_ROT(13) TF_ROT(15) TF_ROT(26) TF_ROT(6)  x0 += k2; x1 += k0 + 5u;
#undef TF_ROT
        g_gumbel[i] = bits_to_gumbel(x0 ^ x1);
    }
}

// preX0[a][r] = dot(Wih0[r,:], emb[a,:]); one block per row r, Wih0 read exactly once
__global__ void k_prex(const float* __restrict__ Wih0, const float* __restrict__ emb) {
    __shared__ float sE[OPS * H];       // 24 KB
    __shared__ float sR[4][OPS];
    const int r = blockIdx.x, tid = threadIdx.x;   // 128 threads
    for (int i = tid; i < OPS * H; i += 128) sE[i] = emb[i];
    __syncthreads();
    float4 w = ((const float4*)(Wih0 + (size_t)r * H))[tid];  // 128*4 = 512
    float acc[OPS];
#pragma unroll
    for (int a = 0; a < OPS; a++) {
        float4 e = ((const float4*)(sE + a * H))[tid];
        acc[a] = (w.x * e.x + w.y * e.y) + (w.z * e.z + w.w * e.w);
    }
    const int lane = tid & 31, wrp = tid >> 5;
#pragma unroll
    for (int a = 0; a < OPS; a++) {
        float v = wsum(acc[a]);
        if (lane == 0) sR[wrp][a] = v;
    }
    __syncthreads();
    if (tid < OPS)
        g_preX0[tid * H4 + r] = (sR[0][tid] + sR[1][tid]) + (sR[2][tid] + sR[3][tid]);
}

// ---------------- the persistent controller kernel ----------------
// SMEM float offsets
#define SM_W0    0
#define SM_WI1   (16 * H)
#define SM_WH1   (32 * H)
#define SM_CW1   (48 * H)            // 24576 .. +2048
#define SM_X     26624
#define SM_Y     27136
#define SM_GATE  27648
#define SM_PREG0 27664
#define SM_PREG1 27680
#define SM_B0    27696
#define SM_B1    27712
#define SM_PREX  27728               // 12*16
#define SM_RED   27920               // 8*4
#define SM_HM    27952
#define SM_C0    27956
#define SM_C1    27960
#define SM_LOG   27964               // 16
#define SM_ACT   27980
#define SM_SAMP  27984               // 2*32: [parity][0..11]=cb2, [16..27]=gumbel
#define SM_W2    28048               // 48
#define SM_CB1   28096               // 4
#define SMEM_FLOATS 28100
#define SMEM_BYTES  (SMEM_FLOATS * 4)

__global__ void __launch_bounds__(TPB, 1) k_ctrl(
    const float* __restrict__ Whh0, const float* __restrict__ Wih1, const float* __restrict__ Whh1,
    const float* __restrict__ c0in,
    const float* __restrict__ cW1, const float* __restrict__ cb1,
    const float* __restrict__ cW2, const float* __restrict__ cb2,
    const unsigned* __restrict__ tempPtr, float* __restrict__ out)
{
    extern __shared__ float sm[];
    float* sW0    = sm + SM_W0;
    float* sWi1   = sm + SM_WI1;
    float* sWh1   = sm + SM_WH1;
    float* sCW1   = sm + SM_CW1;
    float* sX     = sm + SM_X;
    float* sY     = sm + SM_Y;
    float* sGate  = sm + SM_GATE;
    float* sPreG0 = sm + SM_PREG0;
    float* sPreG1 = sm + SM_PREG1;
    float* sB0    = sm + SM_B0;
    float* sB1    = sm + SM_B1;
    float* sPreX  = sm + SM_PREX;
    float* sRed   = sm + SM_RED;
    float* sHm    = sm + SM_HM;
    float* sC0    = sm + SM_C0;
    float* sC1    = sm + SM_C1;
    float* sLog   = sm + SM_LOG;
    int*   sAct   = (int*)(sm + SM_ACT);
    float* sSamp  = sm + SM_SAMP;
    float* sW2    = sm + SM_W2;
    float* sCb1   = sm + SM_CB1;

    const int tid  = threadIdx.x, cta = blockIdx.x;
    const int lane = tid & 31, warp = tid >> 5;
    const int base0 = cta * EPC;
    const uint32_t smem_base = (uint32_t)__cvta_generic_to_shared(sm);

    // ---- prologue: stage weights / constants ----
    for (int idx = tid; idx < 16 * H; idx += TPB) {
        int lr = idx >> 9, col = idx & (H - 1);
        int grow = (lr & 3) * H + base0 + (lr >> 2);   // lr = le*4 + gate (i,f,g,o)
        size_t go = (size_t)grow * H + col;
        sW0[idx]  = Whh0[go];
        sWi1[idx] = Wih1[go];
        sWh1[idx] = Whh1[go];
    }
    sX[tid]       = __ldcg(&g_h0buf[1][tid]);
    sX[tid + 256] = __ldcg(&g_h0buf[1][tid + 256]);
    sY[tid]       = __ldcg(&g_h1buf[1][tid]);
    sY[tid + 256] = __ldcg(&g_h1buf[1][tid + 256]);
    if (tid < 16) {
        int grow = (tid & 3) * H + base0 + (tid >> 2);
        sB0[tid] = g_b0[grow];
        sB1[tid] = g_b1[grow];
    }
    if (tid < OPS * 16) {
        int lr = tid & 15, a = tid >> 4;
        int grow = (lr & 3) * H + base0 + (lr >> 2);
        sPreX[tid] = __ldcg(&g_preX0[a * H4 + grow]);
    }
    if (tid < EPC) {
        sC0[tid] = c0in[base0 + tid];
        sC1[tid] = c0in[H + base0 + tid];
    }
    unsigned tb = tempPtr[0];  // temperature may be int32 or float32
    const float tempf = (tb & 0x7f800000u) ? __uint_as_float(tb) : (float)(int)tb;
    __syncthreads();
    // initial pre-gates: Whh0@h0init, Whh1@h1init (2 rows per warp)
#pragma unroll
    for (int r = 0; r < 2; r++) {
        int row = warp * 2 + r;
        float g0 = dot512(sW0  + row * H, sX);
        float g1 = dot512(sWh1 + row * H, sY);
        if (lane == 0) { sPreG0[row] = g0; sPreG1[row] = g1; }
    }
    __syncthreads();

    for (int s = 0; s < E; s++) {
        const int cur = s & 1, prev = cur ^ 1;

        // ============ PHASE A: sample action (from step s-1) + LSTM0 update ============
        int act = -1;
        if (s > 0) {
            if (warp == 0) waitflags(g_flagC, (unsigned)s);
            __syncthreads();
            // reduce partial logits: warp w -> op w (and op w+8 for w<4)
            {
                float4 v = __ldcg((const float4*)&g_part[warp * GRID + lane * 4]);
                float a = (v.x + v.y) + (v.z + v.w);
                a = wsum(a);
                if (lane == 0) sLog[warp] = (a + sSamp[prev * 32 + warp]) / tempf;
                if (warp < 4) {
                    float4 v2 = __ldcg((const float4*)&g_part[(warp + 8) * GRID + lane * 4]);
                    float a2 = (v2.x + v2.y) + (v2.z + v2.w);
                    a2 = wsum(a2);
                    if (lane == 0) sLog[warp + 8] = (a2 + sSamp[prev * 32 + warp + 8]) / tempf;
                }
            }
            __syncthreads();
            if (warp == 0) {
                const float NEGINF = __int_as_float(0xff800000);
                float logit = (lane < OPS) ? sLog[lane] : NEGINF;
                float m = logit;
#pragma unroll
                for (int o = 16; o; o >>= 1) m = fmaxf(m, __shfl_xor_sync(0xffffffffu, m, o));
                float ex   = (lane < OPS) ? expf(logit - m) : 0.f;
                float ssum = wsum(ex);
                float lse  = m + logf(ssum);
                float lp   = logit - lse;
                float et   = (lane < OPS) ? (-expf(lp) * lp) : 0.f;
                float ent  = wsum(et);
                float key  = (lane < OPS) ? (logit + sSamp[prev * 32 + 16 + lane]) : NEGINF;
                float bk = key; int bi = lane;
#pragma unroll
                for (int o = 16; o; o >>= 1) {
                    float ok = __shfl_xor_sync(0xffffffffu, bk, o);
                    int   oi = __shfl_xor_sync(0xffffffffu, bi, o);
                    if (ok > bk || (ok == bk && oi < bi)) { bk = ok; bi = oi; }
                }
                float lpa = __shfl_sync(0xffffffffu, lp, bi);
                if (lane == 0) {
                    if (cta == 0) {
                        out[s - 1]         = (float)bi;
                        out[E + s - 1]     = lpa;
                        out[2 * E + s - 1] = ent;
                    }
                    sAct[0] = bi;
                }
            }
            __syncthreads();
            act = sAct[0];
        }

        // prefetch for phase C(s) and sampling at phase A(s+1)
        {
            const float* cw1s = cW1 + (size_t)s * H * H + base0;
            cp16(smem_base + (SM_CW1 + tid * 4) * 4,        cw1s + (size_t)tid * H);
            cp16(smem_base + (SM_CW1 + (tid + 256) * 4) * 4, cw1s + (size_t)(tid + 256) * H);
            if (tid == 0)
                cp16(smem_base + SM_CB1 * 4, cb1 + (size_t)s * H + base0);
            else if (tid < 13)
                cp16(smem_base + (SM_W2 + (tid - 1) * 4) * 4,
                     cW2 + ((size_t)s * H + base0) * OPS + (tid - 1) * 4);
            else if (tid < 16)
                cp16(smem_base + (SM_SAMP + cur * 32 + (tid - 13) * 4) * 4,
                     cb2 + s * OPS + (tid - 13) * 4);
            else if (tid < 19)
                cp16(smem_base + (SM_SAMP + cur * 32 + 16 + (tid - 16) * 4) * 4,
                     g_gumbel + s * OPS + (tid - 16) * 4);
            cp_commit();
        }

        // LSTM0 cell update (gates were precomputed: Whh0@h0prev in prior step's shadow)
        if (tid < EPC) {
            float gi = sPreG0[tid * 4 + 0] + sB0[tid * 4 + 0];
            float gf = sPreG0[tid * 4 + 1] + sB0[tid * 4 + 1];
            float gg = sPreG0[tid * 4 + 2] + sB0[tid * 4 + 2];
            float go = sPreG0[tid * 4 + 3] + sB0[tid * 4 + 3];
            if (act >= 0) {
                gi += sPreX[act * 16 + tid * 4 + 0];
                gf += sPreX[act * 16 + tid * 4 + 1];
                gg += sPreX[act * 16 + tid * 4 + 2];
                go += sPreX[act * 16 + tid * 4 + 3];
            }
            float c  = sC0[tid];
            float c2 = sigm(gf) * c + sigm(gi) * tanhf(gg);
            float h2 = sigm(go) * tanhf(c2);
            sC0[tid] = c2;
            g_h0buf[cur][base0 + tid] = h2;
            __syncwarp(0x0000000Fu);
            if (tid == 0) st_rel(&g_flagA[cta * 8], (unsigned)(s + 1));
        }

        // ============ PHASE B: LSTM1 ============
        if (warp == 0) waitflags(g_flagA, (unsigned)(s + 1));
        __syncthreads();
        sX[tid]       = __ldcg(&g_h0buf[cur][tid]);
        sX[tid + 256] = __ldcg(&g_h0buf[cur][tid + 256]);
        __syncthreads();
#pragma unroll
        for (int r = 0; r < 2; r++) {
            int row = warp * 2 + r;
            float g = dot512(sWi1 + row * H, sX);
            if (lane == 0) sGate[row] = g + sPreG1[row] + sB1[row];
        }
        __syncthreads();
        if (tid < EPC) {
            float gi = sGate[tid * 4 + 0], gf = sGate[tid * 4 + 1];
            float gg = sGate[tid * 4 + 2], go = sGate[tid * 4 + 3];
            float c  = sC1[tid];
            float c2 = sigm(gf) * c + sigm(gi) * tanhf(gg);
            float h2 = sigm(go) * tanhf(c2);
            sC1[tid] = c2;
            g_h1buf[cur][base0 + tid] = h2;
            __syncwarp(0x0000000Fu);
            if (tid == 0) st_rel(&g_flagB[cta * 8], (unsigned)(s + 1));
        }
        // shadow (off critical path): Whh0 @ h0new -> pre-gates for step s+1
#pragma unroll
        for (int r = 0; r < 2; r++) {
            int row = warp * 2 + r;
            float g = dot512(sW0 + row * H, sX);
            if (lane == 0) sPreG0[row] = g;
        }

        // ============ PHASE C: controller MLP -> partial logits ============
        if (warp == 0) waitflags(g_flagB, (unsigned)(s + 1));
        __syncthreads();
        cp_wait0();
        sY[tid]       = __ldcg(&g_h1buf[cur][tid]);
        sY[tid + 256] = __ldcg(&g_h1buf[cur][tid + 256]);
        __syncthreads();
        {
            float4 acc = make_float4(0.f, 0.f, 0.f, 0.f);
#pragma unroll
            for (int j = tid; j < H; j += TPB) {
                float4 w = ((const float4*)sCW1)[j];
                float  x = sY[j];
                acc.x = fmaf(x, w.x, acc.x); acc.y = fmaf(x, w.y, acc.y);
                acc.z = fmaf(x, w.z, acc.z); acc.w = fmaf(x, w.w, acc.w);
            }
            acc.x = wsum(acc.x); acc.y = wsum(acc.y);
            acc.z = wsum(acc.z); acc.w = wsum(acc.w);
            if (lane == 0) {
                sRed[warp * 4 + 0] = acc.x; sRed[warp * 4 + 1] = acc.y;
                sRed[warp * 4 + 2] = acc.z; sRed[warp * 4 + 3] = acc.w;
            }
        }
        __syncthreads();
        if (tid < OPS) {
            if (tid < EPC) {
                float v = 0.f;
#pragma unroll
                for (int w = 0; w < 8; w++) v += sRed[w * 4 + tid];
                v += sCb1[tid];
                sHm[tid] = fmaxf(v, 0.f);
            }
            __syncwarp(0x00000FFFu);
            float p = sHm[0] * sW2[0 * OPS + tid];
            p = fmaf(sHm[1], sW2[1 * OPS + tid], p);
            p = fmaf(sHm[2], sW2[2 * OPS + tid], p);
            p = fmaf(sHm[3], sW2[3 * OPS + tid], p);
            g_part[tid * GRID + cta] = p;
            __syncwarp(0x00000FFFu);
            if (tid == 0) st_rel(&g_flagC[cta * 8], (unsigned)(s + 1));
        }
        // shadow: Whh1 @ h1new -> pre-gates for LSTM1 of step s+1
#pragma unroll
        for (int r = 0; r < 2; r++) {
            int row = warp * 2 + r;
            float g = dot512(sWh1 + row * H, sY);
            if (lane == 0) sPreG1[row] = g;
        }
    }

    // ============ epilogue: sample final action (step E-1), CTA0 only ============
    if (cta == 0) {
        const int prev = (E - 1) & 1;
        if (warp == 0) waitflags(g_flagC, (unsigned)E);
        __syncthreads();
        {
            float4 v = __ldcg((const float4*)&g_part[warp * GRID + lane * 4]);
            float a = (v.x + v.y) + (v.z + v.w);
            a = wsum(a);
            if (lane == 0) sLog[warp] = (a + sSamp[prev * 32 + warp]) / tempf;
            if (warp < 4) {
                float4 v2 = __ldcg((const float4*)&g_part[(warp + 8) * GRID + lane * 4]);
                float a2 = (v2.x + v2.y) + (v2.z + v2.w);
                a2 = wsum(a2);
                if (lane == 0) sLog[warp + 8] = (a2 + sSamp[prev * 32 + warp + 8]) / tempf;
            }
        }
        __syncthreads();
        if (warp == 0) {
            const float NEGINF = __int_as_float(0xff800000);
            float logit = (lane < OPS) ? sLog[lane] : NEGINF;
            float m = logit;
#pragma unroll
            for (int o = 16; o; o >>= 1) m = fmaxf(m, __shfl_xor_sync(0xffffffffu, m, o));
            float ex   = (lane < OPS) ? expf(logit - m) : 0.f;
            float ssum = wsum(ex);
            float lse  = m + logf(ssum);
            float lp   = logit - lse;
            float et   = (lane < OPS) ? (-expf(lp) * lp) : 0.f;
            float ent  = wsum(et);
            float key  = (lane < OPS) ? (logit + sSamp[prev * 32 + 16 + lane]) : NEGINF;
            float bk = key; int bi = lane;
#pragma unroll
            for (int o = 16; o; o >>= 1) {
                float ok = __shfl_xor_sync(0xffffffffu, bk, o);
                int   oi = __shfl_xor_sync(0xffffffffu, bi, o);
                if (ok > bk || (ok == bk && oi < bi)) { bk = ok; bi = oi; }
            }
            float lpa = __shfl_sync(0xffffffffu, lp, bi);
            if (lane == 0) {
                out[E - 1]     = (float)bi;
                out[2 * E - 1] = lpa;
                out[3 * E - 1] = ent;
            }
        }
    }
}

// ---------------- launch ----------------
extern "C" void kernel_launch(void* const* d_in, const int* in_sizes, int n_in,
                              void* d_out, int out_size) {
    const unsigned* temp = (const unsigned*)d_in[0];
    const float* h0   = (const float*)d_in[1];
    const float* c0   = (const float*)d_in[2];
    const float* Wih0 = (const float*)d_in[3];
    const float* Whh0 = (const float*)d_in[4];
    const float* bih0 = (const float*)d_in[5];
    const float* bhh0 = (const float*)d_in[6];
    const float* Wih1 = (const float*)d_in[7];
    const float* Whh1 = (const float*)d_in[8];
    const float* bih1 = (const float*)d_in[9];
    const float* bhh1 = (const float*)d_in[10];
    const float* emb  = (const float*)d_in[11];
    const float* cW1  = (const float*)d_in[12];
    const float* cb1  = (const float*)d_in[13];
    const float* cW2  = (const float*)d_in[14];
    const float* cb2  = (const float*)d_in[15];
    float* out = (float*)d_out;

    cudaFuncSetAttribute(k_ctrl, cudaFuncAttributeMaxDynamicSharedMemorySize, SMEM_BYTES);

    k_setup<<<8, 256>>>(h0, bih0, bhh0, bih1, bhh1);
    k_prex<<<H4, 128>>>(Wih0, emb);
    k_ctrl<<<GRID, TPB, SMEM_BYTES>>>(Whh0, Wih1, Whh1, c0, cW1, cb1, cW2, cb2, temp, out);
}

// round 4
// speedup vs baseline: 2.4444x; 1.4031x over previous
#include <cuda_runtime.h>
#include <cstdint>
#include <cstddef>

#define H    512
#define H4   2048
#define E    112
#define OPS  12
#define GRID 128
#define TPB  256
#define EPC  4      // h-elements owned per CTA (128*4 = 512)

#define SENTU 0x7FBADBADu   // NaN payload sentinel; never produced by finite math

// ---------------- persistent device state (re-initialized every launch by k_setup) ----------
__device__ float    g_gumbel[E * OPS];
__device__ float    g_preX0[OPS * H4];            // emb[a] @ Wih0^T
__device__ float    g_b0[H4];                     // bih0 + bhh0
__device__ float    g_b1[H4];                     // bih1 + bhh1
__device__ __align__(16) float g_h0s[E][H];       // per-step h0 broadcast (sentinel-init)
__device__ __align__(16) float g_h1s[E][H];       // per-step h1 broadcast
__device__ __align__(16) float g_parts[E][OPS * GRID]; // per-step partial logits [op][cta]

// ---------------- helpers ----------------
__device__ __forceinline__ float4 poll4(const float* p) {
    float4 v;
    while (true) {
        asm volatile("ld.volatile.global.v4.f32 {%0,%1,%2,%3}, [%4];"
                     : "=f"(v.x), "=f"(v.y), "=f"(v.z), "=f"(v.w) : "l"(p));
        if ((__float_as_uint(v.x) != SENTU) & (__float_as_uint(v.y) != SENTU) &
            (__float_as_uint(v.z) != SENTU) & (__float_as_uint(v.w) != SENTU)) break;
    }
    return v;
}
__device__ __forceinline__ void stv(float* p, float v) {
    asm volatile("st.volatile.global.f32 [%0], %1;" :: "l"(p), "f"(v));
}
__device__ __forceinline__ void cp16(uint32_t dst, const void* src) {
    asm volatile("cp.async.cg.shared.global [%0], [%1], 16;" :: "r"(dst), "l"(src));
}
__device__ __forceinline__ void cp_commit() { asm volatile("cp.async.commit_group;" ::: "memory"); }
__device__ __forceinline__ void cp_wait0()  { asm volatile("cp.async.wait_group 0;" ::: "memory"); }

__device__ __forceinline__ float sigm(float x) { return 1.f / (1.f + expf(-x)); }
__device__ __forceinline__ float wsum(float v) {
#pragma unroll
    for (int o = 16; o; o >>= 1) v += __shfl_xor_sync(0xffffffffu, v, o);
    return v;
}
__device__ __forceinline__ float bits_to_gumbel(unsigned b) {
    float f = __uint_as_float((b >> 9) | 0x3f800000u) - 1.0f;
    float u = fmaxf(1.17549435e-38f, f * 1.0f + 1.17549435e-38f);
    return -logf(-logf(u));
}
// dot(w[0:512], x[0:512]) across the calling warp (all 32 lanes)
__device__ __forceinline__ float dot512(const float* __restrict__ w, const float* __restrict__ x) {
    const int lane = threadIdx.x & 31;
    const float4* wp = (const float4*)w;
    const float4* xp = (const float4*)x;
    float acc = 0.f;
#pragma unroll
    for (int i = lane; i < H / 4; i += 32) {
        float4 u = wp[i], v = xp[i];
        acc = fmaf(u.x, v.x, acc); acc = fmaf(u.y, v.y, acc);
        acc = fmaf(u.z, v.z, acc); acc = fmaf(u.w, v.w, acc);
    }
    return wsum(acc);
}

// ---------------- fused setup kernel (grid-stride) ----------------
#define SENT_N (2 * E * H + E * OPS * GRID)   // 286720
__global__ void k_setup(const float* __restrict__ bih0, const float* __restrict__ bhh0,
                        const float* __restrict__ bih1, const float* __restrict__ bhh1) {
    const float sent = __uint_as_float(SENTU);
    int i = blockIdx.x * blockDim.x + threadIdx.x;
    if (i < E * H) {
        (&g_h0s[0][0])[i] = sent;
        (&g_h1s[0][0])[i] = sent;
    }
    if (i < E * OPS * GRID) (&g_parts[0][0])[i] = sent;
    if (i < H4) {
        g_b0[i] = bih0[i] + bhh0[i];
        g_b1[i] = bih1[i] + bhh1[i];
    }
    if (i < E * OPS) {
        // JAX partitionable threefry: (b1,b2)=threefry2x32((0,42),(0,i)); bits = b1^b2
        const unsigned k0 = 0u, k1 = 42u;
        const unsigned k2 = k0 ^ k1 ^ 0x1BD11BDAu;
        unsigned x0 = 0u + k0;
        unsigned x1 = (unsigned)i + k1;
#define TF_ROT(r) { x0 += x1; x1 = (x1 << (r)) | (x1 >> (32 - (r))); x1 ^= x0; }
        TF_ROT(13) TF_ROT(15) TF_ROT(26) TF_ROT(6)  x0 += k1; x1 += k2 + 1u;
        TF_ROT(17) TF_ROT(29) TF_ROT(16) TF_ROT(24) x0 += k2; x1 += k0 + 2u;
        TF_ROT(13) TF_ROT(15) TF_ROT(26) TF_ROT(6)  x0 += k0; x1 += k1 + 3u;
        TF_ROT(17) TF_ROT(29) TF_ROT(16) TF_ROT(24) x0 += k1; x1 += k2 + 4u;
        TF_ROT(13) TF_ROT(15) TF_ROT(26) TF_ROT(6)  x0 += k2; x1 += k0 + 5u;
#undef TF_ROT
        g_gumbel[i] = bits_to_gumbel(x0 ^ x1);
    }
}

// preX0[a][r] = dot(Wih0[r,:], emb[a,:]); one block per row r, Wih0 read exactly once
__global__ void k_prex(const float* __restrict__ Wih0, const float* __restrict__ emb) {
    __shared__ float sE[OPS * H];       // 24 KB
    __shared__ float sR[4][OPS];
    const int r = blockIdx.x, tid = threadIdx.x;   // 128 threads
    for (int i = tid; i < OPS * H; i += 128) sE[i] = emb[i];
    __syncthreads();
    float4 w = ((const float4*)(Wih0 + (size_t)r * H))[tid];  // 128*4 = 512
    float acc[OPS];
#pragma unroll
    for (int a = 0; a < OPS; a++) {
        float4 e = ((const float4*)(sE + a * H))[tid];
        acc[a] = (w.x * e.x + w.y * e.y) + (w.z * e.z + w.w * e.w);
    }
    const int lane = tid & 31, wrp = tid >> 5;
#pragma unroll
    for (int a = 0; a < OPS; a++) {
        float v = wsum(acc[a]);
        if (lane == 0) sR[wrp][a] = v;
    }
    __syncthreads();
    if (tid < OPS)
        g_preX0[tid * H4 + r] = (sR[0][tid] + sR[1][tid]) + (sR[2][tid] + sR[3][tid]);
}

// ---------------- the persistent controller kernel ----------------
// SMEM float offsets
#define SM_W0    0
#define SM_WI1   (16 * H)
#define SM_WH1   (32 * H)
#define SM_CW1   (48 * H)            // 24576 .. +2048
#define SM_X     26624
#define SM_Y     27136
#define SM_GATE  27648
#define SM_PREG0 27664
#define SM_PREG1 27680
#define SM_B0    27696
#define SM_B1    27712
#define SM_PREX  27728               // 12*16
#define SM_RED   27920               // 8*4
#define SM_HM    27952
#define SM_C0    27956
#define SM_C1    27960
#define SM_LOG   27964               // 16
#define SM_ACT   27980
#define SM_SAMP  27984               // 2*32: [parity][0..11]=cb2, [16..27]=gumbel
#define SM_W2    28048               // 48
#define SM_CB1   28096               // 4
#define SMEM_FLOATS 28100
#define SMEM_BYTES  (SMEM_FLOATS * 4)

__global__ void __launch_bounds__(TPB, 1) k_ctrl(
    const float* __restrict__ Whh0, const float* __restrict__ Wih1, const float* __restrict__ Whh1,
    const float* __restrict__ h0in, const float* __restrict__ c0in,
    const float* __restrict__ cW1, const float* __restrict__ cb1,
    const float* __restrict__ cW2, const float* __restrict__ cb2,
    const unsigned* __restrict__ tempPtr, float* __restrict__ out)
{
    extern __shared__ float sm[];
    float* sW0    = sm + SM_W0;
    float* sWi1   = sm + SM_WI1;
    float* sWh1   = sm + SM_WH1;
    float* sCW1   = sm + SM_CW1;
    float* sX     = sm + SM_X;
    float* sY     = sm + SM_Y;
    float* sGate  = sm + SM_GATE;
    float* sPreG0 = sm + SM_PREG0;
    float* sPreG1 = sm + SM_PREG1;
    float* sB0    = sm + SM_B0;
    float* sB1    = sm + SM_B1;
    float* sPreX  = sm + SM_PREX;
    float* sRed   = sm + SM_RED;
    float* sHm    = sm + SM_HM;
    float* sC0    = sm + SM_C0;
    float* sC1    = sm + SM_C1;
    float* sLog   = sm + SM_LOG;
    int*   sAct   = (int*)(sm + SM_ACT);
    float* sSamp  = sm + SM_SAMP;
    float* sW2    = sm + SM_W2;
    float* sCb1   = sm + SM_CB1;

    const int tid  = threadIdx.x, cta = blockIdx.x;
    const int lane = tid & 31, warp = tid >> 5;
    const int base0 = cta * EPC;
    const uint32_t smem_base = (uint32_t)__cvta_generic_to_shared(sm);
    const float NEGINF = __int_as_float(0xff800000);

    // ---- prologue: stage weights / constants ----
    for (int idx = tid; idx < 16 * H; idx += TPB) {
        int lr = idx >> 9, col = idx & (H - 1);
        int grow = (lr & 3) * H + base0 + (lr >> 2);   // lr = le*4 + gate (i,f,g,o)
        size_t go = (size_t)grow * H + col;
        sW0[idx]  = Whh0[go];
        sWi1[idx] = Wih1[go];
        sWh1[idx] = Whh1[go];
    }
    sX[tid]       = h0in[tid];
    sX[tid + 256] = h0in[tid + 256];
    sY[tid]       = h0in[H + tid];
    sY[tid + 256] = h0in[H + tid + 256];
    if (tid < 16) {
        int grow = (tid & 3) * H + base0 + (tid >> 2);
        sB0[tid] = g_b0[grow];
        sB1[tid] = g_b1[grow];
    }
    if (tid < OPS * 16) {
        int lr = tid & 15, a = tid >> 4;
        int grow = (lr & 3) * H + base0 + (lr >> 2);
        sPreX[tid] = __ldcg(&g_preX0[a * H4 + grow]);
    }
    if (tid < EPC) {
        sC0[tid] = c0in[base0 + tid];
        sC1[tid] = c0in[H + base0 + tid];
    }
    unsigned tb = tempPtr[0];  // temperature may be int32 or float32
    const float tempf = (tb & 0x7f800000u) ? __uint_as_float(tb) : (float)(int)tb;
    __syncthreads();
    // initial pre-gates: Whh0@h0init, Whh1@h1init (2 rows per warp)
#pragma unroll
    for (int r = 0; r < 2; r++) {
        int row = warp * 2 + r;
        float g0 = dot512(sW0  + row * H, sX);
        float g1 = dot512(sWh1 + row * H, sY);
        if (lane == 0) { sPreG0[row] = g0; sPreG1[row] = g1; }
    }
    __syncthreads();

    for (int s = 0; s < E; s++) {
        const int cur = s & 1, prev = cur ^ 1;

        // ---- prefetch for phase C(s) and sampling at phase A(s+1) ----
        {
            const float* cw1s = cW1 + (size_t)s * H * H + base0;
            cp16(smem_base + (SM_CW1 + tid * 4) * 4,         cw1s + (size_t)tid * H);
            cp16(smem_base + (SM_CW1 + (tid + 256) * 4) * 4, cw1s + (size_t)(tid + 256) * H);
            if (tid == 0)
                cp16(smem_base + SM_CB1 * 4, cb1 + (size_t)s * H + base0);
            else if (tid < 13)
                cp16(smem_base + (SM_W2 + (tid - 1) * 4) * 4,
                     cW2 + ((size_t)s * H + base0) * OPS + (tid - 1) * 4);
            else if (tid < 16)
                cp16(smem_base + (SM_SAMP + cur * 32 + (tid - 13) * 4) * 4,
                     cb2 + s * OPS + (tid - 13) * 4);
            else if (tid < 19)
                cp16(smem_base + (SM_SAMP + cur * 32 + 16 + (tid - 16) * 4) * 4,
                     g_gumbel + s * OPS + (tid - 16) * 4);
            cp_commit();
        }

        // ============ PHASE A: sample action of step s-1 (replicated) + LSTM0 ============
        int act = -1;
        if (s > 0) {
            const float* ps = g_parts[s - 1];
            // warp w reduces op w; warps 0-3 also op w+8 (poll fused with read)
            {
                float4 v = poll4(ps + warp * GRID + lane * 4);
                float a = (v.x + v.y) + (v.z + v.w);
                a = wsum(a);
                if (lane == 0) sLog[warp] = (a + sSamp[prev * 32 + warp]) / tempf;
                if (warp < 4) {
                    float4 v2 = poll4(ps + (warp + 8) * GRID + lane * 4);
                    float a2 = (v2.x + v2.y) + (v2.z + v2.w);
                    a2 = wsum(a2);
                    if (lane == 0) sLog[warp + 8] = (a2 + sSamp[prev * 32 + warp + 8]) / tempf;
                }
            }
            __syncthreads();
            if (warp == 0) {  // argmax only — softmax is off the critical path
                float logit = (lane < OPS) ? sLog[lane] : NEGINF;
                float key   = (lane < OPS) ? (logit + sSamp[prev * 32 + 16 + lane]) : NEGINF;
                float bk = key; int bi = lane;
#pragma unroll
                for (int o = 16; o; o >>= 1) {
                    float ok = __shfl_xor_sync(0xffffffffu, bk, o);
                    int   oi = __shfl_xor_sync(0xffffffffu, bi, o);
                    if (ok > bk || (ok == bk && oi < bi)) { bk = ok; bi = oi; }
                }
                if (lane == 0) sAct[0] = bi;
            }
            __syncthreads();
            act = sAct[0];
            // shadow (CTA0 warp7): log-softmax + entropy + outputs for step s-1
            if (cta == 0 && warp == 7) {
                float logit = (lane < OPS) ? sLog[lane] : NEGINF;
                float m = logit;
#pragma unroll
                for (int o = 16; o; o >>= 1) m = fmaxf(m, __shfl_xor_sync(0xffffffffu, m, o));
                float ex   = (lane < OPS) ? expf(logit - m) : 0.f;
                float ssum = wsum(ex);
                float lse  = m + logf(ssum);
                float lp   = logit - lse;
                float et   = (lane < OPS) ? (-expf(lp) * lp) : 0.f;
                float ent  = wsum(et);
                float lpa  = __shfl_sync(0xffffffffu, lp, act);
                if (lane == 0) {
                    out[s - 1]         = (float)act;
                    out[E + s - 1]     = lpa;
                    out[2 * E + s - 1] = ent;
                }
            }
        }

        // LSTM0 cell update (matvec precomputed in prior step's shadow)
        if (tid < EPC) {
            float gi = sPreG0[tid * 4 + 0] + sB0[tid * 4 + 0];
            float gf = sPreG0[tid * 4 + 1] + sB0[tid * 4 + 1];
            float gg = sPreG0[tid * 4 + 2] + sB0[tid * 4 + 2];
            float go = sPreG0[tid * 4 + 3] + sB0[tid * 4 + 3];
            if (act >= 0) {
                gi += sPreX[act * 16 + tid * 4 + 0];
                gf += sPreX[act * 16 + tid * 4 + 1];
                gg += sPreX[act * 16 + tid * 4 + 2];
                go += sPreX[act * 16 + tid * 4 + 3];
            }
            float c  = sC0[tid];
            float c2 = sigm(gf) * c + sigm(gi) * tanhf(gg);
            float h2 = sigm(go) * tanhf(c2);
            sC0[tid] = c2;
            stv(&g_h0s[s][base0 + tid], h2);
        }

        // ============ PHASE B: LSTM1 ============
        if (tid < 128) ((float4*)sX)[tid] = poll4(&g_h0s[s][tid * 4]);
        __syncthreads();
#pragma unroll
        for (int r = 0; r < 2; r++) {
            int row = warp * 2 + r;
            float g = dot512(sWi1 + row * H, sX);
            if (lane == 0) sGate[row] = g + sPreG1[row] + sB1[row];
        }
        __syncthreads();
        if (tid < EPC) {
            float gi = sGate[tid * 4 + 0], gf = sGate[tid * 4 + 1];
            float gg = sGate[tid * 4 + 2], go = sGate[tid * 4 + 3];
            float c  = sC1[tid];
            float c2 = sigm(gf) * c + sigm(gi) * tanhf(gg);
            float h2 = sigm(go) * tanhf(c2);
            sC1[tid] = c2;
            stv(&g_h1s[s][base0 + tid], h2);
        }
        // shadow: Whh0 @ h0new -> pre-gates for step s+1
#pragma unroll
        for (int r = 0; r < 2; r++) {
            int row = warp * 2 + r;
            float g = dot512(sW0 + row * H, sX);
            if (lane == 0) sPreG0[row] = g;
        }

        // ============ PHASE C: controller MLP -> partial logits ============
        cp_wait0();
        if (tid < 128) ((float4*)sY)[tid] = poll4(&g_h1s[s][tid * 4]);
        __syncthreads();
        {
            float4 acc = make_float4(0.f, 0.f, 0.f, 0.f);
#pragma unroll
            for (int j = tid; j < H; j += TPB) {
                float4 w = ((const float4*)sCW1)[j];
                float  x = sY[j];
                acc.x = fmaf(x, w.x, acc.x); acc.y = fmaf(x, w.y, acc.y);
                acc.z = fmaf(x, w.z, acc.z); acc.w = fmaf(x, w.w, acc.w);
            }
            acc.x = wsum(acc.x); acc.y = wsum(acc.y);
            acc.z = wsum(acc.z); acc.w = wsum(acc.w);
            if (lane == 0) {
                sRed[warp * 4 + 0] = acc.x; sRed[warp * 4 + 1] = acc.y;
                sRed[warp * 4 + 2] = acc.z; sRed[warp * 4 + 3] = acc.w;
            }
        }
        __syncthreads();
        if (tid < OPS) {
            if (tid < EPC) {
                float v = 0.f;
#pragma unroll
                for (int w = 0; w < 8; w++) v += sRed[w * 4 + tid];
                v += sCb1[tid];
                sHm[tid] = fmaxf(v, 0.f);
            }
            __syncwarp(0x00000FFFu);
            float p = sHm[0] * sW2[0 * OPS + tid];
            p = fmaf(sHm[1], sW2[1 * OPS + tid], p);
            p = fmaf(sHm[2], sW2[2 * OPS + tid], p);
            p = fmaf(sHm[3], sW2[3 * OPS + tid], p);
            stv(&g_parts[s][tid * GRID + cta], p);
            __syncwarp(0x00000FFFu);
        }
        // shadow: Whh1 @ h1new -> pre-gates for LSTM1 of step s+1
#pragma unroll
        for (int r = 0; r < 2; r++) {
            int row = warp * 2 + r;
            float g = dot512(sWh1 + row * H, sY);
            if (lane == 0) sPreG1[row] = g;
        }
    }

    // ============ epilogue: sample final action (step E-1), CTA0 only ============
    if (cta == 0) {
        const int prevp = (E - 1) & 1;
        const float* ps = g_parts[E - 1];
        {
            float4 v = poll4(ps + warp * GRID + lane * 4);
            float a = (v.x + v.y) + (v.z + v.w);
            a = wsum(a);
            if (lane == 0) sLog[warp] = (a + sSamp[prevp * 32 + warp]) / tempf;
            if (warp < 4) {
                float4 v2 = poll4(ps + (warp + 8) * GRID + lane * 4);
                float a2 = (v2.x + v2.y) + (v2.z + v2.w);
                a2 = wsum(a2);
                if (lane == 0) sLog[warp + 8] = (a2 + sSamp[prevp * 32 + warp + 8]) / tempf;
            }
        }
        __syncthreads();
        if (warp == 0) {
            float logit = (lane < OPS) ? sLog[lane] : NEGINF;
            float m = logit;
#pragma unroll
            for (int o = 16; o; o >>= 1) m = fmaxf(m, __shfl_xor_sync(0xffffffffu, m, o));
            float ex   = (lane < OPS) ? expf(logit - m) : 0.f;
            float ssum = wsum(ex);
            float lse  = m + logf(ssum);
            float lp   = logit - lse;
            float et   = (lane < OPS) ? (-expf(lp) * lp) : 0.f;
            float ent  = wsum(et);
            float key  = (lane < OPS) ? (logit + sSamp[prevp * 32 + 16 + lane]) : NEGINF;
            float bk = key; int bi = lane;
#pragma unroll
            for (int o = 16; o; o >>= 1) {
                float ok = __shfl_xor_sync(0xffffffffu, bk, o);
                int   oi = __shfl_xor_sync(0xffffffffu, bi, o);
                if (ok > bk || (ok == bk && oi < bi)) { bk = ok; bi = oi; }
            }
            float lpa = __shfl_sync(0xffffffffu, lp, bi);
            if (lane == 0) {
                out[E - 1]     = (float)bi;
                out[2 * E - 1] = lpa;
                out[3 * E - 1] = ent;
            }
        }
    }
}

// ---------------- launch ----------------
extern "C" void kernel_launch(void* const* d_in, const int* in_sizes, int n_in,
                              void* d_out, int out_size) {
    const unsigned* temp = (const unsigned*)d_in[0];
    const float* h0   = (const float*)d_in[1];
    const float* c0   = (const float*)d_in[2];
    const float* Wih0 = (const float*)d_in[3];
    const float* Whh0 = (const float*)d_in[4];
    const float* bih0 = (const float*)d_in[5];
    const float* bhh0 = (const float*)d_in[6];
    const float* Wih1 = (const float*)d_in[7];
    const float* Whh1 = (const float*)d_in[8];
    const float* bih1 = (const float*)d_in[9];
    const float* bhh1 = (const float*)d_in[10];
    const float* emb  = (const float*)d_in[11];
    const float* cW1  = (const float*)d_in[12];
    const float* cb1  = (const float*)d_in[13];
    const float* cW2  = (const float*)d_in[14];
    const float* cb2  = (const float*)d_in[15];
    float* out = (float*)d_out;

    cudaFuncSetAttribute(k_ctrl, cudaFuncAttributeMaxDynamicSharedMemorySize, SMEM_BYTES);

    k_setup<<<(E * OPS * GRID + 255) / 256, 256>>>(bih0, bhh0, bih1, bhh1);
    k_prex<<<H4, 128>>>(Wih0, emb);
    k_ctrl<<<GRID, TPB, SMEM_BYTES>>>(Whh0, Wih1, Whh1, h0, c0, cW1, cb1, cW2, cb2, temp, out);
}

// round 6
// speedup vs baseline: 2.8426x; 1.1629x over previous
#include <cuda_runtime.h>
#include <cstdint>
#include <cstddef>

#define H    512
#define H4   2048
#define E    112
#define OPS  12
#define GRID 64
#define TPB  256
#define EPC  8      // h-elements owned per CTA (64*8 = 512)

#define SENTU 0x7FBADBADu   // NaN payload sentinel; never produced by finite math

// ---------------- persistent device state (re-initialized every launch by k_setup) ----------
__device__ float    g_gumbel[E * OPS];
__device__ float    g_preX0[OPS * H4];            // emb[a] @ Wih0^T
__device__ float    g_b0[H4];                     // bih0 + bhh0
__device__ float    g_b1[H4];                     // bih1 + bhh1
__device__ __align__(16) float g_h0s[E][H];       // per-step h0 broadcast (sentinel-init)
__device__ __align__(16) float g_h1s[E][H];       // per-step h1 broadcast
__device__ __align__(16) float g_parts[E][OPS * GRID]; // per-step partial logits [op][cta]

// ---------------- helpers ----------------
__device__ __forceinline__ float4 poll4(const float* p) {
    float4 v;
    while (true) {
        asm volatile("ld.volatile.global.v4.f32 {%0,%1,%2,%3}, [%4];"
                     : "=f"(v.x), "=f"(v.y), "=f"(v.z), "=f"(v.w) : "l"(p));
        if ((__float_as_uint(v.x) != SENTU) & (__float_as_uint(v.y) != SENTU) &
            (__float_as_uint(v.z) != SENTU) & (__float_as_uint(v.w) != SENTU)) break;
    }
    return v;
}
__device__ __forceinline__ void stv(float* p, float v) {
    asm volatile("st.volatile.global.f32 [%0], %1;" :: "l"(p), "f"(v));
}
__device__ __forceinline__ void cp16(uint32_t dst, const void* src) {
    asm volatile("cp.async.cg.shared.global [%0], [%1], 16;" :: "r"(dst), "l"(src));
}
__device__ __forceinline__ void cp_commit() { asm volatile("cp.async.commit_group;" ::: "memory"); }
__device__ __forceinline__ void cp_wait0()  { asm volatile("cp.async.wait_group 0;" ::: "memory"); }

__device__ __forceinline__ float sigm(float x) { return 1.f / (1.f + expf(-x)); }
__device__ __forceinline__ float wsum(float v) {
#pragma unroll
    for (int o = 16; o; o >>= 1) v += __shfl_xor_sync(0xffffffffu, v, o);
    return v;
}
__device__ __forceinline__ float hsum16(float v) {   // reduce within each half-warp
#pragma unroll
    for (int o = 8; o; o >>= 1) v += __shfl_xor_sync(0xffffffffu, v, o);
    return v;   // lanes 0 and 16 hold the two half-sums
}
__device__ __forceinline__ float bits_to_gumbel(unsigned b) {
    float f = __uint_as_float((b >> 9) | 0x3f800000u) - 1.0f;
    float u = fmaxf(1.17549435e-38f, f * 1.0f + 1.17549435e-38f);
    return -logf(-logf(u));
}
// dot(w[0:512], x[0:512]) across the calling warp (all 32 lanes)
__device__ __forceinline__ float dot512(const float* __restrict__ w, const float* __restrict__ x) {
    const int lane = threadIdx.x & 31;
    const float4* wp = (const float4*)w;
    const float4* xp = (const float4*)x;
    float acc = 0.f;
#pragma unroll
    for (int i = lane; i < H / 4; i += 32) {
        float4 u = wp[i], v = xp[i];
        acc = fmaf(u.x, v.x, acc); acc = fmaf(u.y, v.y, acc);
        acc = fmaf(u.z, v.z, acc); acc = fmaf(u.w, v.w, acc);
    }
    return wsum(acc);
}

// ---------------- fused setup kernel (grid-stride) ----------------
__global__ void k_setup(const float* __restrict__ bih0, const float* __restrict__ bhh0,
                        const float* __restrict__ bih1, const float* __restrict__ bhh1) {
    const float sent = __uint_as_float(SENTU);
    int i = blockIdx.x * blockDim.x + threadIdx.x;
    if (i < E * H) {
        (&g_h0s[0][0])[i] = sent;
        (&g_h1s[0][0])[i] = sent;
    }
    if (i < E * OPS * GRID) (&g_parts[0][0])[i] = sent;
    if (i < H4) {
        g_b0[i] = bih0[i] + bhh0[i];
        g_b1[i] = bih1[i] + bhh1[i];
    }
    if (i < E * OPS) {
        // JAX partitionable threefry: (b1,b2)=threefry2x32((0,42),(0,i)); bits = b1^b2
        const unsigned k0 = 0u, k1 = 42u;
        const unsigned k2 = k0 ^ k1 ^ 0x1BD11BDAu;
        unsigned x0 = 0u + k0;
        unsigned x1 = (unsigned)i + k1;
#define TF_ROT(r) { x0 += x1; x1 = (x1 << (r)) | (x1 >> (32 - (r))); x1 ^= x0; }
        TF_ROT(13) TF_ROT(15) TF_ROT(26) TF_ROT(6)  x0 += k1; x1 += k2 + 1u;
        TF_ROT(17) TF_ROT(29) TF_ROT(16) TF_ROT(24) x0 += k2; x1 += k0 + 2u;
        TF_ROT(13) TF_ROT(15) TF_ROT(26) TF_ROT(6)  x0 += k0; x1 += k1 + 3u;
        TF_ROT(17) TF_ROT(29) TF_ROT(16) TF_ROT(24) x0 += k1; x1 += k2 + 4u;
        TF_ROT(13) TF_ROT(15) TF_ROT(26) TF_ROT(6)  x0 += k2; x1 += k0 + 5u;
#undef TF_ROT
        g_gumbel[i] = bits_to_gumbel(x0 ^ x1);
    }
}

// preX0[a][r] = dot(Wih0[r,:], emb[a,:]); one block per row r, Wih0 read exactly once
__global__ void k_prex(const float* __restrict__ Wih0, const float* __restrict__ emb) {
    __shared__ float sE[OPS * H];       // 24 KB
    __shared__ float sR[4][OPS];
    const int r = blockIdx.x, tid = threadIdx.x;   // 128 threads
    for (int i = tid; i < OPS * H; i += 128) sE[i] = emb[i];
    __syncthreads();
    float4 w = ((const float4*)(Wih0 + (size_t)r * H))[tid];  // 128*4 = 512
    float acc[OPS];
#pragma unroll
    for (int a = 0; a < OPS; a++) {
        float4 e = ((const float4*)(sE + a * H))[tid];
        acc[a] = (w.x * e.x + w.y * e.y) + (w.z * e.z + w.w * e.w);
    }
    const int lane = tid & 31, wrp = tid >> 5;
#pragma unroll
    for (int a = 0; a < OPS; a++) {
        float v = wsum(acc[a]);
        if (lane == 0) sR[wrp][a] = v;
    }
    __syncthreads();
    if (tid < OPS)
        g_preX0[tid * H4 + r] = (sR[0][tid] + sR[1][tid]) + (sR[2][tid] + sR[3][tid]);
}

// ---------------- the persistent controller kernel ----------------
// SMEM float offsets (32 gate rows per LSTM matrix; 8 cW1 columns)
#define SM_W0    0                    // 32*512 = 16384
#define SM_WI1   16384
#define SM_WH1   32768
#define SM_CW1   49152                // 512 rows * 8 = 4096
#define SM_X     53248                // 512
#define SM_Y     53760                // 512
#define SM_GATE  54272                // 32
#define SM_PREG0 54304                // 32
#define SM_PREG1 54336                // 32
#define SM_B0    54368                // 32
#define SM_B1    54400                // 32
#define SM_PREX  54432                // 12*32 = 384
#define SM_RED   54816                // 8 warps * 8 = 64
#define SM_HM    54880                // 8
#define SM_C0    54888                // 8
#define SM_C1    54896                // 8
#define SM_LOG   54904                // 16
#define SM_ACT   54920                // 4
#define SM_SAMP  54924                // 2*32: [parity][0..11]=cb2, [16..27]=gumbel
#define SM_W2    54988                // 8*12 = 96
#define SM_CB1   55084                // 8
#define SMEM_FLOATS 55092
#define SMEM_BYTES  (SMEM_FLOATS * 4)   // 220368 B < 227 KB

__global__ void __launch_bounds__(TPB, 1) k_ctrl(
    const float* __restrict__ Whh0, const float* __restrict__ Wih1, const float* __restrict__ Whh1,
    const float* __restrict__ h0in, const float* __restrict__ c0in,
    const float* __restrict__ cW1, const float* __restrict__ cb1,
    const float* __restrict__ cW2, const float* __restrict__ cb2,
    const unsigned* __restrict__ tempPtr, float* __restrict__ out)
{
    extern __shared__ float sm[];
    float* sW0    = sm + SM_W0;
    float* sWi1   = sm + SM_WI1;
    float* sWh1   = sm + SM_WH1;
    float* sCW1   = sm + SM_CW1;
    float* sX     = sm + SM_X;
    float* sY     = sm + SM_Y;
    float* sGate  = sm + SM_GATE;
    float* sPreG0 = sm + SM_PREG0;
    float* sPreG1 = sm + SM_PREG1;
    float* sB0    = sm + SM_B0;
    float* sB1    = sm + SM_B1;
    float* sPreX  = sm + SM_PREX;
    float* sRed   = sm + SM_RED;
    float* sHm    = sm + SM_HM;
    float* sC0    = sm + SM_C0;
    float* sC1    = sm + SM_C1;
    float* sLog   = sm + SM_LOG;
    int*   sAct   = (int*)(sm + SM_ACT);
    float* sSamp  = sm + SM_SAMP;
    float* sW2    = sm + SM_W2;
    float* sCb1   = sm + SM_CB1;

    const int tid  = threadIdx.x, cta = blockIdx.x;
    const int lane = tid & 31, warp = tid >> 5;
    const int base0 = cta * EPC;
    const uint32_t smem_base = (uint32_t)__cvta_generic_to_shared(sm);
    const float NEGINF = __int_as_float(0xff800000);

    // ---- prologue: stage 32 gate rows of each LSTM matrix (float4 copies) ----
    for (int idx = tid; idx < 32 * 128; idx += TPB) {      // 128 float4 per row
        int lr = idx >> 7, c4 = idx & 127;
        int grow = (lr & 3) * H + base0 + (lr >> 2);       // lr = le*4 + gate (i,f,g,o)
        size_t go = (size_t)grow * 128 + c4;               // float4 units
        ((float4*)sW0 )[idx] = ((const float4*)Whh0)[go];
        ((float4*)sWi1)[idx] = ((const float4*)Wih1)[go];
        ((float4*)sWh1)[idx] = ((const float4*)Whh1)[go];
    }
    sX[tid]       = h0in[tid];
    sX[tid + 256] = h0in[tid + 256];
    sY[tid]       = h0in[H + tid];
    sY[tid + 256] = h0in[H + tid + 256];
    if (tid < 32) {
        int grow = (tid & 3) * H + base0 + (tid >> 2);
        sB0[tid] = g_b0[grow];
        sB1[tid] = g_b1[grow];
    }
    for (int idx = tid; idx < OPS * 32; idx += TPB) {      // 384 entries: loop, not guard
        int lr = idx & 31, a = idx >> 5;
        int grow = (lr & 3) * H + base0 + (lr >> 2);
        sPreX[idx] = __ldcg(&g_preX0[a * H4 + grow]);
    }
    if (tid < EPC) {
        sC0[tid] = c0in[base0 + tid];
        sC1[tid] = c0in[H + base0 + tid];
    }
    unsigned tb = tempPtr[0];  // temperature may be int32 or float32
    const float tempf = (tb & 0x7f800000u) ? __uint_as_float(tb) : (float)(int)tb;
    __syncthreads();
    // initial pre-gates: Whh0@h0init, Whh1@h1init (4 rows per warp)
#pragma unroll
    for (int r = 0; r < 4; r++) {
        int row = warp * 4 + r;
        float g0 = dot512(sW0  + row * H, sX);
        float g1 = dot512(sWh1 + row * H, sY);
        if (lane == 0) { sPreG0[row] = g0; sPreG1[row] = g1; }
    }
    __syncthreads();

    for (int s = 0; s < E; s++) {
        const int cur = s & 1, prev = cur ^ 1;

        // ============ PHASE A: sample action of step s-1 (replicated) + LSTM0 ============
        int act = -1;
        if (s > 0) {
            const float* ps = g_parts[s - 1];
            if (warp < 6) {   // warps 0-5: two ops each via half-warps
                int op = warp * 2 + (lane >> 4);
                float4 v = poll4(ps + op * GRID + (lane & 15) * 4);
                float a = (v.x + v.y) + (v.z + v.w);
                a = hsum16(a);
                if ((lane & 15) == 0) sLog[op] = (a + sSamp[prev * 32 + op]) / tempf;
            }
            __syncthreads();
            if (warp == 0) {  // argmax only — softmax is off the critical path
                float logit = (lane < OPS) ? sLog[lane] : NEGINF;
                float key   = (lane < OPS) ? (logit + sSamp[prev * 32 + 16 + lane]) : NEGINF;
                float bk = key; int bi = lane;
#pragma unroll
                for (int o = 16; o; o >>= 1) {
                    float ok = __shfl_xor_sync(0xffffffffu, bk, o);
                    int   oi = __shfl_xor_sync(0xffffffffu, bi, o);
                    if (ok > bk || (ok == bk && oi < bi)) { bk = ok; bi = oi; }
                }
                if (lane == 0) sAct[0] = bi;
            }
            __syncthreads();
            act = sAct[0];
            // shadow (CTA0 warp7): log-softmax + entropy + outputs for step s-1
            if (cta == 0 && warp == 7) {
                float logit = (lane < OPS) ? sLog[lane] : NEGINF;
                float m = logit;
#pragma unroll
                for (int o = 16; o; o >>= 1) m = fmaxf(m, __shfl_xor_sync(0xffffffffu, m, o));
                float ex   = (lane < OPS) ? expf(logit - m) : 0.f;
                float ssum = wsum(ex);
                float lse  = m + logf(ssum);
                float lp   = logit - lse;
                float et   = (lane < OPS) ? (-expf(lp) * lp) : 0.f;
                float ent  = wsum(et);
                float lpa  = __shfl_sync(0xffffffffu, lp, act);
                if (lane == 0) {
                    out[s - 1]         = (float)act;
                    out[E + s - 1]     = lpa;
                    out[2 * E + s - 1] = ent;
                }
            }
        }

        // ---- prefetch for phase C(s) / sampling at A(s+1) — AFTER the gating poll ----
        {
            const float* cw1s = cW1 + (size_t)s * H * H + base0;
            cp16(smem_base + (SM_CW1 + tid * 8) * 4,             cw1s + (size_t)tid * H);
            cp16(smem_base + (SM_CW1 + tid * 8 + 4) * 4,         cw1s + (size_t)tid * H + 4);
            cp16(smem_base + (SM_CW1 + (tid + 256) * 8) * 4,     cw1s + (size_t)(tid + 256) * H);
            cp16(smem_base + (SM_CW1 + (tid + 256) * 8 + 4) * 4, cw1s + (size_t)(tid + 256) * H + 4);
            if (tid < 2)
                cp16(smem_base + (SM_CB1 + tid * 4) * 4, cb1 + (size_t)s * H + base0 + tid * 4);
            else if (tid < 26)   // 24 cp16 = 96 floats = full EPC*OPS W2 slice
                cp16(smem_base + (SM_W2 + (tid - 2) * 4) * 4,
                     cW2 + ((size_t)s * H + base0) * OPS + (tid - 2) * 4);
            else if (tid < 29)
                cp16(smem_base + (SM_SAMP + cur * 32 + (tid - 26) * 4) * 4,
                     cb2 + s * OPS + (tid - 26) * 4);
            else if (tid < 32)
                cp16(smem_base + (SM_SAMP + cur * 32 + 16 + (tid - 29) * 4) * 4,
                     g_gumbel + s * OPS + (tid - 29) * 4);
            cp_commit();
        }

        // LSTM0 cell update (matvec precomputed in prior step's shadow)
        if (tid < EPC) {
            float gi = sPreG0[tid * 4 + 0] + sB0[tid * 4 + 0];
            float gf = sPreG0[tid * 4 + 1] + sB0[tid * 4 + 1];
            float gg = sPreG0[tid * 4 + 2] + sB0[tid * 4 + 2];
            float go = sPreG0[tid * 4 + 3] + sB0[tid * 4 + 3];
            if (act >= 0) {
                gi += sPreX[act * 32 + tid * 4 + 0];
                gf += sPreX[act * 32 + tid * 4 + 1];
                gg += sPreX[act * 32 + tid * 4 + 2];
                go += sPreX[act * 32 + tid * 4 + 3];
            }
            float c  = sC0[tid];
            float c2 = sigm(gf) * c + sigm(gi) * tanhf(gg);
            float h2 = sigm(go) * tanhf(c2);
            sC0[tid] = c2;
            stv(&g_h0s[s][base0 + tid], h2);
        }

        // ============ PHASE B: LSTM1 ============
        if (tid < 128) ((float4*)sX)[tid] = poll4(&g_h0s[s][tid * 4]);
        __syncthreads();
#pragma unroll
        for (int r = 0; r < 4; r++) {
            int row = warp * 4 + r;
            float g = dot512(sWi1 + row * H, sX);
            if (lane == 0) sGate[row] = g + sPreG1[row] + sB1[row];
        }
        __syncthreads();
        if (tid < EPC) {
            float gi = sGate[tid * 4 + 0], gf = sGate[tid * 4 + 1];
            float gg = sGate[tid * 4 + 2], go = sGate[tid * 4 + 3];
            float c  = sC1[tid];
            float c2 = sigm(gf) * c + sigm(gi) * tanhf(gg);
            float h2 = sigm(go) * tanhf(c2);
            sC1[tid] = c2;
            stv(&g_h1s[s][base0 + tid], h2);
        }
        // shadow: Whh0 @ h0new -> pre-gates for step s+1
#pragma unroll
        for (int r = 0; r < 4; r++) {
            int row = warp * 4 + r;
            float g = dot512(sW0 + row * H, sX);
            if (lane == 0) sPreG0[row] = g;
        }

        // ============ PHASE C: controller MLP -> partial logits ============
        cp_wait0();
        if (tid < 128) ((float4*)sY)[tid] = poll4(&g_h1s[s][tid * 4]);
        __syncthreads();
        {
            float4 a0 = make_float4(0.f, 0.f, 0.f, 0.f);
            float4 a1 = make_float4(0.f, 0.f, 0.f, 0.f);
#pragma unroll
            for (int jj = 0; jj < 2; jj++) {
                int j = tid + jj * 256;
                float4 w0 = ((const float4*)sCW1)[j * 2];
                float4 w1 = ((const float4*)sCW1)[j * 2 + 1];
                float  x  = sY[j];
                a0.x = fmaf(x, w0.x, a0.x); a0.y = fmaf(x, w0.y, a0.y);
                a0.z = fmaf(x, w0.z, a0.z); a0.w = fmaf(x, w0.w, a0.w);
                a1.x = fmaf(x, w1.x, a1.x); a1.y = fmaf(x, w1.y, a1.y);
                a1.z = fmaf(x, w1.z, a1.z); a1.w = fmaf(x, w1.w, a1.w);
            }
            a0.x = wsum(a0.x); a0.y = wsum(a0.y); a0.z = wsum(a0.z); a0.w = wsum(a0.w);
            a1.x = wsum(a1.x); a1.y = wsum(a1.y); a1.z = wsum(a1.z); a1.w = wsum(a1.w);
            if (lane == 0) {
                sRed[warp * 8 + 0] = a0.x; sRed[warp * 8 + 1] = a0.y;
                sRed[warp * 8 + 2] = a0.z; sRed[warp * 8 + 3] = a0.w;
                sRed[warp * 8 + 4] = a1.x; sRed[warp * 8 + 5] = a1.y;
                sRed[warp * 8 + 6] = a1.z; sRed[warp * 8 + 7] = a1.w;
            }
        }
        __syncthreads();
        if (tid < OPS) {
            if (tid < EPC) {
                float v = 0.f;
#pragma unroll
                for (int w = 0; w < 8; w++) v += sRed[w * 8 + tid];
                v += sCb1[tid];
                sHm[tid] = fmaxf(v, 0.f);
            }
            __syncwarp(0x00000FFFu);
            float p = sHm[0] * sW2[0 * OPS + tid];
#pragma unroll
            for (int k = 1; k < EPC; k++) p = fmaf(sHm[k], sW2[k * OPS + tid], p);
            stv(&g_parts[s][tid * GRID + cta], p);
            __syncwarp(0x00000FFFu);
        }
        // shadow: Whh1 @ h1new -> pre-gates for LSTM1 of step s+1
#pragma unroll
        for (int r = 0; r < 4; r++) {
            int row = warp * 4 + r;
            float g = dot512(sWh1 + row * H, sY);
            if (lane == 0) sPreG1[row] = g;
        }
    }

    // ============ epilogue: sample final action (step E-1), CTA0 only ============
    if (cta == 0) {
        const int prevp = (E - 1) & 1;
        const float* ps = g_parts[E - 1];
        if (warp < 6) {
            int op = warp * 2 + (lane >> 4);
            float4 v = poll4(ps + op * GRID + (lane & 15) * 4);
            float a = (v.x + v.y) + (v.z + v.w);
            a = hsum16(a);
            if ((lane & 15) == 0) sLog[op] = (a + sSamp[prevp * 32 + op]) / tempf;
        }
        __syncthreads();
        if (warp == 0) {
            float logit = (lane < OPS) ? sLog[lane] : NEGINF;
            float m = logit;
#pragma unroll
            for (int o = 16; o; o >>= 1) m = fmaxf(m, __shfl_xor_sync(0xffffffffu, m, o));
            float ex   = (lane < OPS) ? expf(logit - m) : 0.f;
            float ssum = wsum(ex);
            float lse  = m + logf(ssum);
            float lp   = logit - lse;
            float et   = (lane < OPS) ? (-expf(lp) * lp) : 0.f;
            float ent  = wsum(et);
            float key  = (lane < OPS) ? (logit + sSamp[prevp * 32 + 16 + lane]) : NEGINF;
            float bk = key; int bi = lane;
#pragma unroll
            for (int o = 16; o; o >>= 1) {
                float ok = __shfl_xor_sync(0xffffffffu, bk, o);
                int   oi = __shfl_xor_sync(0xffffffffu, bi, o);
                if (ok > bk || (ok == bk && oi < bi)) { bk = ok; bi = oi; }
            }
            float lpa = __shfl_sync(0xffffffffu, lp, bi);
            if (lane == 0) {
                out[E - 1]     = (float)bi;
                out[2 * E - 1] = lpa;
                out[3 * E - 1] = ent;
            }
        }
    }
}

// ---------------- launch ----------------
extern "C" void kernel_launch(void* const* d_in, const int* in_sizes, int n_in,
                              void* d_out, int out_size) {
    const unsigned* temp = (const unsigned*)d_in[0];
    const float* h0   = (const float*)d_in[1];
    const float* c0   = (const float*)d_in[2];
    const float* Wih0 = (const float*)d_in[3];
    const float* Whh0 = (const float*)d_in[4];
    const float* bih0 = (const float*)d_in[5];
    const float* bhh0 = (const float*)d_in[6];
    const float* Wih1 = (const float*)d_in[7];
    const float* Whh1 = (const float*)d_in[8];
    const float* bih1 = (const float*)d_in[9];
    const float* bhh1 = (const float*)d_in[10];
    const float* emb  = (const float*)d_in[11];
    const float* cW1  = (const float*)d_in[12];
    const float* cb1  = (const float*)d_in[13];
    const float* cW2  = (const float*)d_in[14];
    const float* cb2  = (const float*)d_in[15];
    float* out = (float*)d_out;

    cudaFuncSetAttribute(k_ctrl, cudaFuncAttributeMaxDynamicSharedMemorySize, SMEM_BYTES);

    k_setup<<<(E * OPS * GRID + 255) / 256, 256>>>(bih0, bhh0, bih1, bhh1);
    k_prex<<<H4, 128>>>(Wih0, emb);
    k_ctrl<<<GRID, TPB, SMEM_BYTES>>>(Whh0, Wih1, Whh1, h0, c0, cW1, cb1, cW2, cb2, temp, out);
}